// round 17
// baseline (speedup 1.0000x reference)
#include <cuda_runtime.h>
#include <cuda_bf16.h>
#include <cuda_pipeline.h>
#include <math.h>
#include <cstdint>

// Problem constants (fixed by the reference setup)
#define NB   128
#define LL   256
#define NN   (NB*LL)      // 32768 nodes
#define DIN  1024
#define HH   256
#define CC   7
#define WIN  4

// GEMM tiling: BK=32, 3-stage ring; B pre-transposed [N][K] -> LDSM for both operands
#define BM 128
#define BN 128
#define BK 32
#define TPITCH 36         // floats per smem tile row (32 + 4 pad -> conflict-free LDSM)
#define NSTAGES 3
#define ST (BM*TPITCH)    // 4608 floats per tile stage (A and B identical geometry)
#define SMEM_BYTES ((NSTAGES*2*ST)*4)   // 110592 -> 2 CTAs/SM (221KB < 228KB)

// ---------------- scratch (device globals; no allocation allowed) ----------
__device__ __align__(256) float g_Ain[(size_t)NN * DIN];      // tf32-rounded input
__device__ __align__(256) float g_t_all[(size_t)NN * 1024];   // [t0|t1|root|skip]
__device__ __align__(256) float g_hc[(size_t)NN * 512];       // [neigh | h] tf32-rounded
__device__ __align__(256) float g_z[(size_t)NN * HH];
__device__ __align__(256) float g_B1t[1024 * 1024];           // Bcat1 transposed [n][k] tf32
__device__ __align__(256) float g_B2t[256 * 512];             // Bcat2 transposed [n][k] tf32
__device__ float g_loss;

__device__ __forceinline__ float to_tf32(float x) {
    unsigned u;
    asm("cvt.rna.tf32.f32 %0, %1;" : "=r"(u) : "f"(x));
    return __uint_as_float(u);
}

// ---------------- PTX wrappers ---------------------------------------------
__device__ __forceinline__ void ldsm_x4(uint32_t& r0, uint32_t& r1, uint32_t& r2, uint32_t& r3,
                                        uint32_t addr) {
    asm volatile("ldmatrix.sync.aligned.m8n8.x4.shared.b16 {%0,%1,%2,%3}, [%4];"
                 : "=r"(r0), "=r"(r1), "=r"(r2), "=r"(r3)
                 : "r"(addr));
}
__device__ __forceinline__ void mma_tf32(float& c0, float& c1, float& c2, float& c3,
                                         uint32_t a0, uint32_t a1, uint32_t a2, uint32_t a3,
                                         uint32_t b0, uint32_t b1) {
    asm volatile("mma.sync.aligned.m16n8k8.row.col.f32.tf32.tf32.f32 "
                 "{%0,%1,%2,%3}, {%4,%5,%6,%7}, {%8,%9}, {%0,%1,%2,%3};"
                 : "+f"(c0), "+f"(c1), "+f"(c2), "+f"(c3)
                 : "r"(a0), "r"(a1), "r"(a2), "r"(a3), "r"(b0), "r"(b1));
}

// ---------------- prep: transposed tf32 weights [n][k], zero loss ----------
__global__ void prep_kernel(const float* __restrict__ Wrgcn,
                            const float* __restrict__ Wroot,
                            const float* __restrict__ Wskip,
                            const float* __restrict__ Wrel,
                            const float* __restrict__ Wgrt) {
    int idx = blockIdx.x * blockDim.x + threadIdx.x;
    if (idx == 0) g_loss = 0.0f;
    // B1t[n][k], n in 0..1023 (4 groups of 256 output cols), k in 0..1023
    if (idx < 1024 * 1024) {
        int n = idx >> 10, k = idx & 1023;
        int g = n >> 8, c = n & 255;
        float v;
        if      (g == 0) v = Wrgcn[k * 256 + c];
        else if (g == 1) v = Wrgcn[262144 + k * 256 + c];
        else if (g == 2) v = Wroot[k * 256 + c];
        else             v = Wskip[k * 256 + c];
        g_B1t[idx] = to_tf32(v);
    }
    // B2t[n][k], n in 0..255, k in 0..511 (k<256: Wrel, else Wgrt)
    if (idx < 256 * 512) {
        int n = idx >> 9, k = idx & 511;
        float v = (k < 256) ? Wrel[k * 256 + n] : Wgrt[(k - 256) * 256 + n];
        g_B2t[idx] = to_tf32(v);
    }
}

// ---------------- tf32-round the input matrix ------------------------------
__global__ void cvtA_kernel(const float4* __restrict__ in, float4* __restrict__ out) {
    int n4 = NN * DIN / 4;
    for (int i = blockIdx.x * blockDim.x + threadIdx.x; i < n4; i += gridDim.x * blockDim.x) {
        float4 v = in[i];
        v.x = to_tf32(v.x); v.y = to_tf32(v.y);
        v.z = to_tf32(v.z); v.w = to_tf32(v.w);
        out[i] = v;
    }
}

// ---------------- TF32 mma.sync GEMM: A[M][K] @ Bt[N][K]^T -----------------
// Both tiles 128 rows x 32 k in smem (pitch 36); LDSM for A and B fragments.
// blockIdx.x = N tile (fast-varying -> concurrent column tiles reuse A via L2)
__global__ __launch_bounds__(256, 2)
void tf32gemm(const float* __restrict__ A, const float* __restrict__ Bt,
              float* __restrict__ C, int M, int N, int K) {
    extern __shared__ float smbuf[];
    float* Asm = smbuf;
    float* Bsm = smbuf + NSTAGES * ST;

    const int tid  = threadIdx.x;
    const int lane = tid & 31, wid = tid >> 5;
    const int wm = wid >> 2, wn = wid & 3;       // 2 (m) x 4 (n) warps; warp tile 64x32
    const int mBase = blockIdx.y * BM;
    const int nBase = blockIdx.x * BN;

    const uint32_t sA_u = (uint32_t)__cvta_generic_to_shared(Asm);
    const uint32_t sB_u = (uint32_t)__cvta_generic_to_shared(Bsm);

    const int KT = K / BK;

    float acc[4][4][4];
#pragma unroll
    for (int i = 0; i < 4; i++)
#pragma unroll
        for (int j = 0; j < 4; j++)
#pragma unroll
            for (int k = 0; k < 4; k++) acc[i][j][k] = 0.0f;

    // loader: each tile = 128 rows x 8 float4; 1024 float4; 4 chunks/thread/tile
    int trow[4], tcol[4];
#pragma unroll
    for (int i = 0; i < 4; i++) {
        int idx = tid + i * 256;
        trow[i] = idx >> 3;            // 0..127
        tcol[i] = (idx & 7) << 2;      // 0,4,...,28
    }

    // prefetch NSTAGES-1 stages
#pragma unroll
    for (int s = 0; s < NSTAGES - 1; s++) {
        int k0 = s * BK;
#pragma unroll
        for (int i = 0; i < 4; i++) {
            __pipeline_memcpy_async(Asm + s * ST + trow[i] * TPITCH + tcol[i],
                                    A  + (size_t)(mBase + trow[i]) * K + k0 + tcol[i], 16);
            __pipeline_memcpy_async(Bsm + s * ST + trow[i] * TPITCH + tcol[i],
                                    Bt + (size_t)(nBase + trow[i]) * K + k0 + tcol[i], 16);
        }
        __pipeline_commit();
    }

    // A ldmatrix lane mapping (a0..a3 of m16n8k8)
    const int lm_row = (lane & 7) + ((lane >> 3) & 1) * 8;
    const int lm_col = (lane >> 4) * 4;
    const uint32_t lmA = sA_u + (uint32_t)((wm * 64 + lm_row) * TPITCH + lm_col) * 4u;
    // B ldmatrix lane mapping: matrix j = n-block j (8 rows each); row addr = wn*32 + lane
    const uint32_t lmB = sB_u + (uint32_t)((wn * 32 + lane) * TPITCH) * 4u;

    int st = 0;
    for (int kt = 0; kt < KT; kt++) {
        __pipeline_wait_prior(NSTAGES - 2);
        __syncthreads();
        const uint32_t aBase = lmA + (uint32_t)(st * ST) * 4u;
        const uint32_t bBase = lmB + (uint32_t)(st * ST) * 4u;

#pragma unroll
        for (int ks = 0; ks < 4; ks++) {
            uint32_t afr[4][4];
#pragma unroll
            for (int mf = 0; mf < 4; mf++) {
                uint32_t ad = aBase + (uint32_t)(mf * 16 * TPITCH + ks * 8) * 4u;
                ldsm_x4(afr[mf][0], afr[mf][1], afr[mf][2], afr[mf][3], ad);
            }
            // B fragments: two LDSM.x4 -> b0[nf], b1[nf] for nf=0..3
            uint32_t b0[4], b1[4];
            ldsm_x4(b0[0], b0[1], b0[2], b0[3], bBase + (uint32_t)(ks * 8) * 4u);
            ldsm_x4(b1[0], b1[1], b1[2], b1[3], bBase + (uint32_t)(ks * 8 + 4) * 4u);
#pragma unroll
            for (int mf = 0; mf < 4; mf++)
#pragma unroll
                for (int nf = 0; nf < 4; nf++)
                    mma_tf32(acc[mf][nf][0], acc[mf][nf][1], acc[mf][nf][2], acc[mf][nf][3],
                             afr[mf][0], afr[mf][1], afr[mf][2], afr[mf][3],
                             b0[nf], b1[nf]);
        }

        int ktn = kt + NSTAGES - 1;
        if (ktn < KT) {
            int s = ktn % NSTAGES;
            int k0 = ktn * BK;
#pragma unroll
            for (int i = 0; i < 4; i++) {
                __pipeline_memcpy_async(Asm + s * ST + trow[i] * TPITCH + tcol[i],
                                        A  + (size_t)(mBase + trow[i]) * K + k0 + tcol[i], 16);
                __pipeline_memcpy_async(Bsm + s * ST + trow[i] * TPITCH + tcol[i],
                                        Bt + (size_t)(nBase + trow[i]) * K + k0 + tcol[i], 16);
            }
        }
        __pipeline_commit();

        st++; if (st == NSTAGES) st = 0;
    }

    // epilogue: c frag layout -> float2 stores
#pragma unroll
    for (int mf = 0; mf < 4; mf++) {
        int r = mBase + wm * 64 + mf * 16 + (lane >> 2);
#pragma unroll
        for (int nf = 0; nf < 4; nf++) {
            int cc = nBase + wn * 32 + nf * 8 + (lane & 3) * 2;
            *(float2*)&C[(size_t)r * N + cc]       = make_float2(acc[mf][nf][0], acc[mf][nf][1]);
            *(float2*)&C[(size_t)(r + 8) * N + cc] = make_float2(acc[mf][nf][2], acc[mf][nf][3]);
        }
    }
}

// ---------------- RGCN window aggregation (mean per relation) --------------
// one block per node, 128 threads, float2 per thread (measured 43us)
__global__ void rgcn_agg(const int* __restrict__ spk, const float* __restrict__ b_rgcn) {
    int i = blockIdx.x;
    int c = threadIdx.x * 2;
    int p = i & (LL - 1);
    int dlo = (p < WIN) ? -p : -WIN;
    int dhi = ((LL - 1 - p) < WIN) ? (LL - 1 - p) : WIN;
    int si = spk[i];
    float s0x = 0.f, s0y = 0.f, s1x = 0.f, s1y = 0.f;
    int c0 = 0, c1 = 0;
    for (int d = dlo; d <= dhi; d++) {
        int j = i + d;
        int r = si & spk[j];
        float2 v = *(const float2*)&g_t_all[(size_t)j * 1024 + r * 256 + c];
        if (r) { s1x += v.x; s1y += v.y; c1++; } else { s0x += v.x; s0y += v.y; c0++; }
    }
    float inv0 = 1.0f / (float)(c0 > 0 ? c0 : 1);
    float inv1 = 1.0f / (float)(c1 > 0 ? c1 : 1);
    float2 root = *(const float2*)&g_t_all[(size_t)i * 1024 + 512 + c];
    float2 bb   = *(const float2*)&b_rgcn[c];
    float hx = root.x + bb.x + s0x * inv0 + s1x * inv1;
    float hy = root.y + bb.y + s0y * inv0 + s1y * inv1;
    *(float2*)&g_hc[(size_t)i * 512 + 256 + c] = make_float2(to_tf32(hx), to_tf32(hy));
}

// ---------------- GraphConv neighbor add-aggregation (float4) --------------
__global__ void graph_sum() {
    int i = blockIdx.x;
    int c = threadIdx.x * 4;
    int p = i & (LL - 1);
    int dlo = (p < WIN) ? -p : -WIN;
    int dhi = ((LL - 1 - p) < WIN) ? (LL - 1 - p) : WIN;
    float sx = 0.f, sy = 0.f, sz = 0.f, sw = 0.f;
    for (int d = dlo; d <= dhi; d++) {
        float4 v = *(const float4*)&g_hc[(size_t)(i + d) * 512 + 256 + c];
        sx += v.x; sy += v.y; sz += v.z; sw += v.w;
    }
    *(float4*)&g_hc[(size_t)i * 512 + c] =
        make_float4(to_tf32(sx), to_tf32(sy), to_tf32(sz), to_tf32(sw));
}

// ---------------- classifier + cross-entropy loss --------------------------
__global__ void classify_loss(const float* __restrict__ b_rel,
                              const float* __restrict__ b_skip,
                              const float* __restrict__ W_cls,
                              const float* __restrict__ b_cls,
                              const int* __restrict__ labels,
                              float* __restrict__ out_logits) {
    int n = blockIdx.x * 8 + (threadIdx.x >> 5);
    int lane = threadIdx.x & 31;
    const float* zrow = g_z + (size_t)n * HH;
    const float* srow = g_t_all + (size_t)n * 1024 + 768;

    float acc[CC] = {0.f, 0.f, 0.f, 0.f, 0.f, 0.f, 0.f};
    for (int e = lane; e < HH; e += 32) {
        float pre = zrow[e] + srow[e] + b_rel[e] + b_skip[e];
#pragma unroll
        for (int cix = 0; cix < CC; cix++) acc[cix] = fmaf(pre, W_cls[e * CC + cix], acc[cix]);
    }
#pragma unroll
    for (int off = 16; off; off >>= 1)
#pragma unroll
        for (int cix = 0; cix < CC; cix++) acc[cix] += __shfl_xor_sync(0xffffffffu, acc[cix], off);
#pragma unroll
    for (int cix = 0; cix < CC; cix++) acc[cix] += b_cls[cix];

    if (out_logits != nullptr && lane < CC)
        out_logits[(size_t)n * CC + lane] = acc[lane];

    __shared__ float wloss[8];
    if (lane == 0) {
        float m = acc[0];
#pragma unroll
        for (int cix = 1; cix < CC; cix++) m = fmaxf(m, acc[cix]);
        float s = 0.f;
#pragma unroll
        for (int cix = 0; cix < CC; cix++) s += expf(acc[cix] - m);
        float lse = m + logf(s);
        wloss[threadIdx.x >> 5] = lse - acc[labels[n]];
    }
    __syncthreads();
    if (threadIdx.x == 0) {
        float t = 0.f;
#pragma unroll
        for (int w = 0; w < 8; w++) t += wloss[w];
        atomicAdd(&g_loss, t);
    }
}

__global__ void finalize_loss(float* __restrict__ dst) {
    *dst = g_loss * (1.0f / (float)NN);
}

// ---------------- host launcher --------------------------------------------
template <typename T>
static T* sym_addr(const void* sym) {
    void* p = nullptr;
    cudaGetSymbolAddress(&p, sym);
    return (T*)p;
}

extern "C" void kernel_launch(void* const* d_in, const int* in_sizes, int n_in,
                              void* d_out, int out_size) {
    const float* input    = (const float*)d_in[0];
    const int*   speakers = (const int*)d_in[2];
    const int*   labels   = (const int*)d_in[3];
    const float* W_rgcn   = (const float*)d_in[6];
    const float* W_root   = (const float*)d_in[7];
    const float* b_rgcn   = (const float*)d_in[8];
    const float* W_rel    = (const float*)d_in[9];
    const float* b_rel    = (const float*)d_in[10];
    const float* W_grt    = (const float*)d_in[11];
    const float* W_skip   = (const float*)d_in[12];
    const float* b_skip   = (const float*)d_in[13];
    const float* W_cls    = (const float*)d_in[14];
    const float* b_cls    = (const float*)d_in[15];
    float* out = (float*)d_out;

    float* Ain   = sym_addr<float>(g_Ain);
    float* t_all = sym_addr<float>(g_t_all);
    float* hc    = sym_addr<float>(g_hc);
    float* z     = sym_addr<float>(g_z);
    float* B1t   = sym_addr<float>(g_B1t);
    float* B2t   = sym_addr<float>(g_B2t);

    cudaFuncSetAttribute(tf32gemm, cudaFuncAttributeMaxDynamicSharedMemorySize, SMEM_BYTES);

    // 1) weight transpose+round (tf32) + loss zero
    prep_kernel<<<4096, 256>>>(W_rgcn, W_root, W_skip, W_rel, W_grt);

    // 2) tf32-round the input matrix
    cvtA_kernel<<<2048, 256>>>((const float4*)input, (float4*)Ain);

    // 3) fused input GEMM: [32768,1024] @ B1t[1024,1024]^T
    tf32gemm<<<dim3(1024 / BN, NN / BM), 256, SMEM_BYTES>>>(Ain, B1t, t_all, NN, 1024, DIN);

    // 4) RGCN window mean-aggregation -> h (float2 vectorized)
    rgcn_agg<<<NN, HH / 2>>>(speakers, b_rgcn);

    // 5) GraphConv window add-aggregation -> neigh (float4 vectorized)
    graph_sum<<<NN, HH / 4>>>();

    // 6) [neigh|h] @ B2t[256,512]^T
    tf32gemm<<<dim3(256 / BN, NN / BM), 256, SMEM_BYTES>>>(hc, B2t, z, NN, 256, 512);

    // 7) classifier + loss
    float* logits = (out_size >= NN * CC) ? out : nullptr;
    classify_loss<<<NN / 8, 256>>>(b_rel, b_skip, W_cls, b_cls, labels, logits);

    // 8) loss scalar placement
    if (out_size == NN * CC + 1)       finalize_loss<<<1, 1>>>(out + (size_t)NN * CC);
    else if (out_size < NN * CC)       finalize_loss<<<1, 1>>>(out);
}